// round 12
// baseline (speedup 1.0000x reference)
#include <cuda_runtime.h>
#include <cuda_bf16.h>

#define B_    2
#define T_    4096
#define H_    16
#define DK_   128
#define DV_   128
#define HID_  2048
#define C_    64
#define N_    64
#define ROWS_ 131072
#define NTASK_ 2048

// ---------- device scratch ----------
__device__ float g_qn[(size_t)ROWS_ * DK_];
__device__ float g_kn[(size_t)ROWS_ * DK_];
__device__ float g_beta[(size_t)ROWS_];
__device__ float g_gsw[(size_t)ROWS_];
__device__ float g_u[(size_t)NTASK_ * C_ * DV_];
__device__ float g_wq[(size_t)NTASK_ * C_ * 256];   // [task][row][w0..127|q0..127]
__device__ float g_attn[(size_t)NTASK_ * C_ * C_];
__device__ float g_o[(size_t)ROWS_ * DV_];

typedef unsigned long long u64;
__device__ __forceinline__ u64 pk2(float lo, float hi) {
    u64 r; asm("mov.b64 %0, {%1, %2};" : "=l"(r) : "f"(lo), "f"(hi)); return r;
}
__device__ __forceinline__ void fma2(u64 &d, u64 a, u64 b) {
    asm("fma.rn.f32x2 %0, %1, %2, %0;" : "+l"(d) : "l"(a), "l"(b));
}
__device__ __forceinline__ float2 up2(u64 v) {
    float lo, hi; asm("mov.b64 {%0, %1}, %2;" : "=f"(lo), "=f"(hi) : "l"(v));
    return make_float2(lo, hi);
}
__device__ __forceinline__ unsigned su32(const void* p) {
    return (unsigned)__cvta_generic_to_shared(p);
}
__device__ __forceinline__ void cpa16(const void* dst, const float* src) {
    asm volatile("cp.async.cg.shared.global [%0], [%1], 16;" :: "r"(su32(dst)), "l"(src));
}
#define CPA_COMMIT() asm volatile("cp.async.commit_group;" ::: "memory")
#define CPA_WAIT1()  asm volatile("cp.async.wait_group 1;" ::: "memory")
#define CPA_WAIT0()  asm volatile("cp.async.wait_group 0;" ::: "memory")

// ============ K1: beta / swish-gate projections (4 rows/block) ============
__global__ __launch_bounds__(256) void proj_kernel(
    const float* __restrict__ hab, const float* __restrict__ hg,
    const float* __restrict__ Wb,  const float* __restrict__ Wg)
{
    int row0 = blockIdx.x * 4;
    int which = blockIdx.y;
    const float* hb = (which ? hg : hab) + (size_t)row0 * HID_;
    const float* W  = which ? Wg : Wb;
    u64 acc[4][8] = {};
    for (int j = threadIdx.x; j < HID_; j += 256) {
        const float4* wr = (const float4*)(W + (size_t)j * 16);
        float4 w0 = __ldg(wr+0), w1 = __ldg(wr+1), w2 = __ldg(wr+2), w3 = __ldg(wr+3);
        u64 wp[8];
        wp[0]=pk2(w0.x,w0.y); wp[1]=pk2(w0.z,w0.w);
        wp[2]=pk2(w1.x,w1.y); wp[3]=pk2(w1.z,w1.w);
        wp[4]=pk2(w2.x,w2.y); wp[5]=pk2(w2.z,w2.w);
        wp[6]=pk2(w3.x,w3.y); wp[7]=pk2(w3.z,w3.w);
#pragma unroll
        for (int r = 0; r < 4; r++) {
            float x = __ldg(hb + (size_t)r * HID_ + j);
            u64 X = pk2(x, x);
#pragma unroll
            for (int p = 0; p < 8; p++) fma2(acc[r][p], X, wp[p]);
        }
    }
    float a[4][16];
#pragma unroll
    for (int r = 0; r < 4; r++)
#pragma unroll
        for (int p = 0; p < 8; p++) {
            float2 t = up2(acc[r][p]);
            a[r][2*p] = t.x; a[r][2*p+1] = t.y;
        }
#pragma unroll
    for (int r = 0; r < 4; r++)
#pragma unroll
        for (int o = 0; o < 16; o++)
#pragma unroll
            for (int off = 16; off; off >>= 1)
                a[r][o] += __shfl_xor_sync(0xffffffffu, a[r][o], off);
    __shared__ float red[8][64];
    int warp = threadIdx.x >> 5, lane = threadIdx.x & 31;
    if (lane == 0)
#pragma unroll
        for (int r = 0; r < 4; r++)
#pragma unroll
            for (int o = 0; o < 16; o++) red[warp][r*16+o] = a[r][o];
    __syncthreads();
    if (threadIdx.x < 64) {
        float s = 0.f;
#pragma unroll
        for (int w = 0; w < 8; w++) s += red[w][threadIdx.x];
        int r = threadIdx.x >> 4, o = threadIdx.x & 15;
        float sg = 1.f / (1.f + __expf(-s));
        if (which == 0) g_beta[(size_t)(row0+r) * 16 + o] = sg;
        else            g_gsw [(size_t)(row0+r) * 16 + o] = s * sg;
    }
}

// ============ K2: l2 norm ============
__global__ __launch_bounds__(256) void l2norm_kernel(
    const float* __restrict__ q, const float* __restrict__ k)
{
    int gw = (blockIdx.x << 3) + (threadIdx.x >> 5);
    int lane = threadIdx.x & 31;
    int which = (gw >= ROWS_) ? 1 : 0;
    int r = which ? (gw - ROWS_) : gw;
    const float* src = which ? k : q;
    float* dst = which ? g_kn : g_qn;
    float4 v = *(const float4*)(src + (size_t)r * 128 + lane * 4);
    float s = v.x*v.x + v.y*v.y + v.z*v.z + v.w*v.w;
#pragma unroll
    for (int off = 16; off; off >>= 1) s += __shfl_xor_sync(0xffffffffu, s, off);
    float inv = rsqrtf(s + 1e-6f);
    if (!which) inv *= 0.08838834764831845f;
    v.x *= inv; v.y *= inv; v.z *= inv; v.w *= inv;
    *(float4*)(dst + (size_t)r * 128 + lane * 4) = v;
}

// ============ K3: per-chunk UT transform (w/q emitted to split-half g_wq) ============
#define CHUNK_SMEM ((128*68 + 64*132 + 64*68 + 64*68 + 64) * 4)
__global__ __launch_bounds__(256) void chunk_kernel(const float* __restrict__ v)
{
    extern __shared__ float sm[];
    float* sKT = sm;               // [128][68]
    float* sBuf= sKT + 128*68;     // [64][132]  staging K -> V -> Q
    float* sL  = sBuf + 64*132;    // [64][68]
    float* sT  = sL + 64*68;       // [64][68]
    float* sb  = sT + 64*68;       // [64]
    int idx = blockIdx.x;
    int n = idx & 63, h = (idx >> 6) & 15, b = idx >> 10;
    int t0 = n * 64;
    int tid = threadIdx.x;
    size_t rowbase = ((size_t)(b * T_ + t0) * H_ + h) * 128;

    // 1: K via cp.async
#pragma unroll
    for (int i = 0; i < 8; i++) {
        int f = tid + i*256; int row = f >> 5, c4 = f & 31;
        cpa16(&sBuf[row*132 + c4*4], &g_kn[rowbase + (size_t)row*2048 + c4*4]);
    }
    CPA_COMMIT();
    if (tid < 64) sb[tid] = g_beta[(size_t)(b*T_ + t0 + tid) * H_ + h];
    CPA_WAIT0(); __syncthreads();

    // 2: transpose -> sKT
    for (int e = tid; e < 2048; e += 256) {
        int c = e & 127, rb = e >> 7;
        float4 vv;
        vv.x = sBuf[(rb*4+0)*132 + c]; vv.y = sBuf[(rb*4+1)*132 + c];
        vv.z = sBuf[(rb*4+2)*132 + c]; vv.w = sBuf[(rb*4+3)*132 + c];
        *(float4*)&sKT[c*68 + rb*4] = vv;
    }
    __syncthreads();

    // 3: L = diag(beta) * strict_tril(K K^T)
    int ty = tid >> 4, tx = tid & 15;
    if (tx <= ty) {
        int r0 = ty*4, c0 = tx*4;
        u64 a[4][2] = {};
        for (int kk = 0; kk < 128; kk++) {
            const float* rp = &sKT[kk*68];
            float4 av = *(const float4*)(rp + r0);
            ulonglong2 bp = *(const ulonglong2*)(rp + c0);
            u64 A;
            A = pk2(av.x,av.x); fma2(a[0][0],A,bp.x); fma2(a[0][1],A,bp.y);
            A = pk2(av.y,av.y); fma2(a[1][0],A,bp.x); fma2(a[1][1],A,bp.y);
            A = pk2(av.z,av.z); fma2(a[2][0],A,bp.x); fma2(a[2][1],A,bp.y);
            A = pk2(av.w,av.w); fma2(a[3][0],A,bp.x); fma2(a[3][1],A,bp.y);
        }
#pragma unroll
        for (int i = 0; i < 4; i++) {
            int rr = r0 + i; float br = sb[rr];
            float2 p0 = up2(a[i][0]), p1 = up2(a[i][1]);
            float vals[4] = {p0.x, p0.y, p1.x, p1.y};
#pragma unroll
            for (int j = 0; j < 4; j++) {
                int cc = c0 + j;
                sL[rr*68 + cc] = (cc < rr) ? br * vals[j] : 0.f;
            }
        }
    }
    __syncthreads();

    // 4: (I+L) T' = diag(beta), forward substitution
    if (tid < 64) {
        int c = tid; float bc = sb[c];
        for (int i = 0; i < 64; i++) {
            const float* Li = &sL[i*68];
            float v0 = 0.f, v1 = 0.f, v2 = 0.f, v3 = 0.f;
            int j = c;
            for (; j + 3 < i; j += 4) {
                v0 -= Li[j  ] * sT[(j  )*68 + c];
                v1 -= Li[j+1] * sT[(j+1)*68 + c];
                v2 -= Li[j+2] * sT[(j+2)*68 + c];
                v3 -= Li[j+3] * sT[(j+3)*68 + c];
            }
            for (; j < i; j++) v0 -= Li[j] * sT[j*68 + c];
            sT[i*68 + c] = ((i == c) ? bc : 0.f) + v0 + v1 + v2 + v3;
        }
    }
    __syncthreads();

    int wid = tid >> 5, lane = tid & 31;
    // 5: w = T' @ K -> g_wq w-half (sBuf still holds K)
    {
        int r0 = wid*8, c0 = lane*4;
        u64 acc[8][2] = {};
        for (int j = 0; j < 64; j++) {
            ulonglong2 bp = *(const ulonglong2*)&sBuf[j*132 + c0];
#pragma unroll
            for (int i = 0; i < 8; i++) {
                float a = sT[(r0+i)*68 + j];
                u64 A = pk2(a,a);
                fma2(acc[i][0],A,bp.x); fma2(acc[i][1],A,bp.y);
            }
        }
#pragma unroll
        for (int i = 0; i < 8; i++) {
            float2 p0 = up2(acc[i][0]), p1 = up2(acc[i][1]);
            *(float4*)&g_wq[(size_t)idx*16384 + (size_t)(r0+i)*256 + c0] =
                make_float4(p0.x,p0.y,p1.x,p1.y);
        }
    }
    __syncthreads();

    // 6: V via cp.async
#pragma unroll
    for (int i = 0; i < 8; i++) {
        int f = tid + i*256; int row = f >> 5, c4 = f & 31;
        cpa16(&sBuf[row*132 + c4*4], &v[rowbase + (size_t)row*2048 + c4*4]);
    }
    CPA_COMMIT(); CPA_WAIT0(); __syncthreads();

    // 7: u = T' @ V
    {
        int r0 = wid*8, c0 = lane*4;
        u64 acc[8][2] = {};
        for (int j = 0; j < 64; j++) {
            ulonglong2 bp = *(const ulonglong2*)&sBuf[j*132 + c0];
#pragma unroll
            for (int i = 0; i < 8; i++) {
                float a = sT[(r0+i)*68 + j];
                u64 A = pk2(a,a);
                fma2(acc[i][0],A,bp.x); fma2(acc[i][1],A,bp.y);
            }
        }
#pragma unroll
        for (int i = 0; i < 8; i++) {
            float2 p0 = up2(acc[i][0]), p1 = up2(acc[i][1]);
            *(float4*)&g_u[(size_t)idx*8192 + (r0+i)*128 + c0] =
                make_float4(p0.x,p0.y,p1.x,p1.y);
        }
    }
    __syncthreads();

    // 8: Q via cp.async
#pragma unroll
    for (int i = 0; i < 8; i++) {
        int f = tid + i*256; int row = f >> 5, c4 = f & 31;
        cpa16(&sBuf[row*132 + c4*4], &g_qn[rowbase + (size_t)row*2048 + c4*4]);
    }
    CPA_COMMIT(); CPA_WAIT0(); __syncthreads();

    // 8.5: q copy -> g_wq q-half (coalesced)
    for (int e = tid; e < 2048; e += 256) {
        int row = e >> 5, c4 = e & 31;
        float4 qv = *(const float4*)&sBuf[row*132 + c4*4];
        *(float4*)&g_wq[(size_t)idx*16384 + (size_t)row*256 + 128 + c4*4] = qv;
    }

    // 9: attn = tril(Q K^T)
    {
        int r0 = ty*4, c0 = tx*4;
        if (tx <= ty) {
            u64 a[4][2] = {};
            for (int kk = 0; kk < 128; kk++) {
                ulonglong2 bp = *(const ulonglong2*)&sKT[kk*68 + c0];
                float q0 = sBuf[(r0+0)*132 + kk];
                float q1 = sBuf[(r0+1)*132 + kk];
                float q2 = sBuf[(r0+2)*132 + kk];
                float q3 = sBuf[(r0+3)*132 + kk];
                u64 A;
                A = pk2(q0,q0); fma2(a[0][0],A,bp.x); fma2(a[0][1],A,bp.y);
                A = pk2(q1,q1); fma2(a[1][0],A,bp.x); fma2(a[1][1],A,bp.y);
                A = pk2(q2,q2); fma2(a[2][0],A,bp.x); fma2(a[2][1],A,bp.y);
                A = pk2(q3,q3); fma2(a[3][0],A,bp.x); fma2(a[3][1],A,bp.y);
            }
#pragma unroll
            for (int i = 0; i < 4; i++) {
                float2 p0 = up2(a[i][0]), p1 = up2(a[i][1]);
                float vals[4] = {p0.x, p0.y, p1.x, p1.y};
#pragma unroll
                for (int j = 0; j < 4; j++)
                    g_attn[(size_t)idx*4096 + (r0+i)*64 + c0+j] =
                        (c0+j <= r0+i) ? vals[j] : 0.f;
            }
        } else {
#pragma unroll
            for (int i = 0; i < 4; i++)
#pragma unroll
                for (int j = 0; j < 4; j++)
                    g_attn[(size_t)idx*4096 + (r0+i)*64 + c0+j] = 0.f;
        }
    }
}

// ============ K4: inter-chunk scan (512 thr, r1c4 A/B, 2-krow C) ============
#define SCAN_SMEM ((128*36 + 64*264 + 64*132 + 64*68 + 64*36) * 4)
__global__ __launch_bounds__(512) void scan_kernel()
{
    extern __shared__ float sm[];
    float* sS  = sm;                // [128][36]
    float* sWQ = sS  + 128*36;      // [64][264]  (256 data + 8 pad)
    float* sK  = sWQ + 64*264;      // [64][132]
    float* sA  = sK  + 64*132;      // [64][68]
    float* sVi = sA  + 64*68;       // [64][36]

    int vg = blockIdx.x, h = blockIdx.y, b = blockIdx.z;
    int v0 = vg * 32;
    int tid = threadIdx.x;
    int rq = tid >> 3, c0 = (tid & 7) * 4;   // rq in [0,64): 1 row per thread
    int k0 = rq * 2;                         // phase C: 2 k-rows
    int taskbase = (b*16 + h) * 64;

    for (int e = tid; e < 128*36; e += 512) sS[e] = 0.f;
    u64 sreg[2][2] = {};

    // prologue: G1 = {WQ,A}(0), G2 = {K}(0)
    {
        size_t rb0 = ((size_t)(b*T_) * H_ + h) * 128;
#pragma unroll
        for (int i = 0; i < 8; i++) {
            int f = tid + i*512;
            int row = f >> 6, jj = f & 63;
            cpa16(&sWQ[row*264 + jj*4], g_wq + (size_t)taskbase*16384 + f*4);
        }
#pragma unroll
        for (int i = 0; i < 2; i++) {
            int f = tid + i*512;
            cpa16(&sA[(f>>4)*68 + (f&15)*4], g_attn + (size_t)taskbase*4096 + f*4);
        }
        CPA_COMMIT();
#pragma unroll
        for (int i = 0; i < 4; i++) {
            int f = tid + i*512; int row = f >> 5, c4 = f & 31;
            cpa16(&sK[row*132 + c4*4], g_kn + rb0 + (size_t)row*2048 + c4*4);
        }
        CPA_COMMIT();
    }
    float4 ruA;
    {
        size_t ub = (size_t)taskbase*8192 + (size_t)rq*128 + v0 + c0;
        ruA = *(const float4*)&g_u[ub];
    }

    for (int n = 0; n < 64; n++) {
        int np = min(n + 1, 63);
        int taskp = taskbase + np;
        size_t rowbase  = ((size_t)(b*T_ + n*64)  * H_ + h) * 128;

        CPA_WAIT1();               // WQ,A(n) ready
        __syncthreads();

        // prefetch u(n+1)
        float4 ruA2;
        {
            size_t ub = (size_t)taskp*8192 + (size_t)rq*128 + v0 + c0;
            ruA2 = *(const float4*)&g_u[ub];
        }

        // ---- phase A: vi = u - w@S ; partial o = q@S ----
        u64 aw0=0, aw1=0, aq0=0, aq1=0;
        {
            const float* wr = &sWQ[rq*264];
            const float* qr = wr + 128;
            for (int k = 0; k < 128; k += 4) {
                ulonglong2 s0 = *(const ulonglong2*)&sS[(k  )*36 + c0];
                ulonglong2 s1 = *(const ulonglong2*)&sS[(k+1)*36 + c0];
                ulonglong2 s2 = *(const ulonglong2*)&sS[(k+2)*36 + c0];
                ulonglong2 s3 = *(const ulonglong2*)&sS[(k+3)*36 + c0];
                float4 w = *(const float4*)&wr[k];
                float4 q = *(const float4*)&qr[k];
                u64 A;
                A = pk2(w.x,w.x); fma2(aw0,A,s0.x); fma2(aw1,A,s0.y);
                A = pk2(q.x,q.x); fma2(aq0,A,s0.x); fma2(aq1,A,s0.y);
                A = pk2(w.y,w.y); fma2(aw0,A,s1.x); fma2(aw1,A,s1.y);
                A = pk2(q.y,q.y); fma2(aq0,A,s1.x); fma2(aq1,A,s1.y);
                A = pk2(w.z,w.z); fma2(aw0,A,s2.x); fma2(aw1,A,s2.y);
                A = pk2(q.z,q.z); fma2(aq0,A,s2.x); fma2(aq1,A,s2.y);
                A = pk2(w.w,w.w); fma2(aw0,A,s3.x); fma2(aw1,A,s3.y);
                A = pk2(q.w,q.w); fma2(aq0,A,s3.x); fma2(aq1,A,s3.y);
            }
        }
        {
            float2 p0 = up2(aw0), p1 = up2(aw1);
            *(float4*)&sVi[rq*36 + c0] =
                make_float4(ruA.x - p0.x, ruA.y - p0.y, ruA.z - p1.x, ruA.w - p1.y);
        }
        ruA = ruA2;
        __syncthreads();           // sVi published

        // ---- phase B: o = q@S + attn @ vi (j <= rq; attn upper is 0) ----
        {
            const float* ar = &sA[rq*68];
            for (int j = 0; j <= rq; j++) {
                ulonglong2 vv = *(const ulonglong2*)&sVi[j*36 + c0];
                float a0 = ar[j];
                u64 A0 = pk2(a0,a0); fma2(aq0,A0,vv.x); fma2(aq1,A0,vv.y);
            }
            float2 p0 = up2(aq0), p1 = up2(aq1);
            size_t ob = rowbase + (size_t)rq*2048 + v0 + c0;
            *(float4*)&g_o[ob] = make_float4(p0.x, p0.y, p1.x, p1.y);
        }
        __syncthreads();           // sA,sWQ dead -> refill

        // issue G1(n+1) = {WQ,A}
#pragma unroll
        for (int i = 0; i < 8; i++) {
            int f = tid + i*512;
            int row = f >> 6, jj = f & 63;
            cpa16(&sWQ[row*264 + jj*4], g_wq + (size_t)taskp*16384 + f*4);
        }
#pragma unroll
        for (int i = 0; i < 2; i++) {
            int f = tid + i*512;
            cpa16(&sA[(f>>4)*68 + (f&15)*4], g_attn + (size_t)taskp*4096 + f*4);
        }
        CPA_COMMIT();

        CPA_WAIT1();               // K(n) ready
        __syncthreads();

        // ---- phase C: S += K^T @ vi (2-krow register tile) ----
        {
#pragma unroll 4
            for (int c = 0; c < 64; c++) {
                float2 kv = *(const float2*)&sK[c*132 + k0];
                float4 vv = *(const float4*)&sVi[c*36 + c0];
                u64 vp0 = pk2(vv.x, vv.y), vp1 = pk2(vv.z, vv.w);
                u64 A;
                A = pk2(kv.x,kv.x); fma2(sreg[0][0], A, vp0); fma2(sreg[0][1], A, vp1);
                A = pk2(kv.y,kv.y); fma2(sreg[1][0], A, vp0); fma2(sreg[1][1], A, vp1);
            }
#pragma unroll
            for (int i = 0; i < 2; i++) {
                float2 a = up2(sreg[i][0]), bb = up2(sreg[i][1]);
                *(float4*)&sS[(k0+i)*36 + c0] = make_float4(a.x, a.y, bb.x, bb.y);
            }
        }
        __syncthreads();           // sK reads done -> refill

        // issue G2(n+1) = {K}
        {
            size_t rowbasep = ((size_t)(b*T_ + np*64) * H_ + h) * 128;
#pragma unroll
            for (int i = 0; i < 4; i++) {
                int f = tid + i*512; int row = f >> 5, c4 = f & 31;
                cpa16(&sK[row*132 + c4*4], g_kn + rowbasep + (size_t)row*2048 + c4*4);
            }
            CPA_COMMIT();
        }
    }
}

// ============ K5: RMSNorm * gate + per-head projection ============
#define OUT_SMEM ((128*132 + 64*132) * 4)
__global__ __launch_bounds__(256) void out_kernel(
    const float* __restrict__ norm_w, const float* __restrict__ proj,
    float* __restrict__ out)
{
    extern __shared__ float sm[];
    float* sP = sm;
    float* sO = sP + 128*132;
    int h = blockIdx.y;
    int tid = threadIdx.x, wid = tid >> 5, lane = tid & 31;
    const float* Ph = proj + (size_t)h * 16384;
    for (int e = tid; e < 4096; e += 256) {
        int row = e >> 5, c4 = e & 31;
        *(float4*)&sP[row*132 + c4*4] = *(const float4*)&Ph[row*128 + c4*4];
    }
    float4 nw = *(const float4*)&norm_w[lane*4];
    __syncthreads();

    for (int grp = 0; grp < 2; grp++) {
        int bt0 = blockIdx.x*128 + grp*64;
        int wr = wid * 8;
        for (int i = 0; i < 8; i++) {
            int bt = bt0 + wr + i;
            size_t ob = ((size_t)bt * H_ + h) * 128;
            float4 ov = *(const float4*)&g_o[ob + lane*4];
            float ss = ov.x*ov.x + ov.y*ov.y + ov.z*ov.z + ov.w*ov.w;
#pragma unroll
            for (int off = 16; off; off >>= 1)
                ss += __shfl_xor_sync(0xffffffffu, ss, off);
            float rms = rsqrtf(ss * (1.f/128.f) + 1e-5f);
            float s = rms * g_gsw[(size_t)bt * H_ + h];
            float* orow = &sO[(wr+i)*132];
            orow[lane*4+0] = ov.x * s * nw.x;
            orow[lane*4+1] = ov.y * s * nw.y;
            orow[lane*4+2] = ov.z * s * nw.z;
            orow[lane*4+3] = ov.w * s * nw.w;
        }
        __syncwarp();
        u64 acc[8][2] = {};
        for (int vv = 0; vv < 128; vv++) {
            float4 p = *(const float4*)&sP[vv*132 + lane*4];
            u64 p01 = pk2(p.x, p.y), p23 = pk2(p.z, p.w);
#pragma unroll
            for (int i = 0; i < 8; i++) {
                float ovv = sO[(wr+i)*132 + vv];
                u64 A = pk2(ovv, ovv);
                fma2(acc[i][0], A, p01);
                fma2(acc[i][1], A, p23);
            }
        }
#pragma unroll
        for (int i = 0; i < 8; i++) {
            int bt = bt0 + wr + i;
            float2 p0 = up2(acc[i][0]), p1 = up2(acc[i][1]);
            *(float4*)&out[(size_t)bt*2048 + h*128 + lane*4] =
                make_float4(p0.x, p0.y, p1.x, p1.y);
        }
        __syncwarp();
    }
}

// ============ launch ============
extern "C" void kernel_launch(void* const* d_in, const int* in_sizes, int n_in,
                              void* d_out, int out_size)
{
    const float* hab  = (const float*)d_in[0];
    const float* hg   = (const float*)d_in[1];
    const float* q    = (const float*)d_in[2];
    const float* k    = (const float*)d_in[3];
    const float* v    = (const float*)d_in[4];
    const float* Wb   = (const float*)d_in[5];
    const float* Wg   = (const float*)d_in[6];
    const float* onw  = (const float*)d_in[7];
    const float* proj = (const float*)d_in[8];
    float* out = (float*)d_out;

    cudaFuncSetAttribute(chunk_kernel, cudaFuncAttributeMaxDynamicSharedMemorySize, CHUNK_SMEM);
    cudaFuncSetAttribute(scan_kernel,  cudaFuncAttributeMaxDynamicSharedMemorySize, SCAN_SMEM);
    cudaFuncSetAttribute(out_kernel,   cudaFuncAttributeMaxDynamicSharedMemorySize, OUT_SMEM);

    proj_kernel<<<dim3(B_*T_/4, 2), 256>>>(hab, hg, Wb, Wg);
    l2norm_kernel<<<(2*ROWS_)/8, 256>>>(q, k);
    chunk_kernel<<<NTASK_, 256, CHUNK_SMEM>>>(v);
    scan_kernel<<<dim3(4, H_, B_), 512, SCAN_SMEM>>>();
    out_kernel<<<dim3(64, H_), 256, OUT_SMEM>>>(onw, proj, out);
}

// round 14
// speedup vs baseline: 1.2263x; 1.2263x over previous
#include <cuda_runtime.h>
#include <cuda_bf16.h>

#define B_    2
#define T_    4096
#define H_    16
#define DK_   128
#define DV_   128
#define HID_  2048
#define C_    64
#define N_    64
#define ROWS_ 131072
#define NTASK_ 2048

// ---------- device scratch ----------
__device__ float g_qn[(size_t)ROWS_ * DK_];
__device__ float g_kn[(size_t)ROWS_ * DK_];
__device__ float g_beta[(size_t)ROWS_];
__device__ float g_gsw[(size_t)ROWS_];
__device__ float g_u[(size_t)NTASK_ * C_ * DV_];
__device__ float g_wq[(size_t)NTASK_ * C_ * 256];   // [task][row][w0..127|q0..127]
__device__ float g_attn[(size_t)NTASK_ * C_ * C_];
__device__ float g_o[(size_t)ROWS_ * DV_];

typedef unsigned long long u64;
__device__ __forceinline__ u64 pk2(float lo, float hi) {
    u64 r; asm("mov.b64 %0, {%1, %2};" : "=l"(r) : "f"(lo), "f"(hi)); return r;
}
__device__ __forceinline__ void fma2(u64 &d, u64 a, u64 b) {
    asm("fma.rn.f32x2 %0, %1, %2, %0;" : "+l"(d) : "l"(a), "l"(b));
}
__device__ __forceinline__ float2 up2(u64 v) {
    float lo, hi; asm("mov.b64 {%0, %1}, %2;" : "=f"(lo), "=f"(hi) : "l"(v));
    return make_float2(lo, hi);
}
__device__ __forceinline__ unsigned su32(const void* p) {
    return (unsigned)__cvta_generic_to_shared(p);
}
__device__ __forceinline__ void cpa16(const void* dst, const float* src) {
    asm volatile("cp.async.cg.shared.global [%0], [%1], 16;" :: "r"(su32(dst)), "l"(src));
}
#define CPA_COMMIT() asm volatile("cp.async.commit_group;" ::: "memory")
#define CPA_WAIT1()  asm volatile("cp.async.wait_group 1;" ::: "memory")
#define CPA_WAIT0()  asm volatile("cp.async.wait_group 0;" ::: "memory")

// ============ K1: beta / swish-gate projections (4 rows/block) ============
__global__ __launch_bounds__(256) void proj_kernel(
    const float* __restrict__ hab, const float* __restrict__ hg,
    const float* __restrict__ Wb,  const float* __restrict__ Wg)
{
    int row0 = blockIdx.x * 4;
    int which = blockIdx.y;
    const float* hb = (which ? hg : hab) + (size_t)row0 * HID_;
    const float* W  = which ? Wg : Wb;
    u64 acc[4][8] = {};
    for (int j = threadIdx.x; j < HID_; j += 256) {
        const float4* wr = (const float4*)(W + (size_t)j * 16);
        float4 w0 = __ldg(wr+0), w1 = __ldg(wr+1), w2 = __ldg(wr+2), w3 = __ldg(wr+3);
        u64 wp[8];
        wp[0]=pk2(w0.x,w0.y); wp[1]=pk2(w0.z,w0.w);
        wp[2]=pk2(w1.x,w1.y); wp[3]=pk2(w1.z,w1.w);
        wp[4]=pk2(w2.x,w2.y); wp[5]=pk2(w2.z,w2.w);
        wp[6]=pk2(w3.x,w3.y); wp[7]=pk2(w3.z,w3.w);
#pragma unroll
        for (int r = 0; r < 4; r++) {
            float x = __ldg(hb + (size_t)r * HID_ + j);
            u64 X = pk2(x, x);
#pragma unroll
            for (int p = 0; p < 8; p++) fma2(acc[r][p], X, wp[p]);
        }
    }
    float a[4][16];
#pragma unroll
    for (int r = 0; r < 4; r++)
#pragma unroll
        for (int p = 0; p < 8; p++) {
            float2 t = up2(acc[r][p]);
            a[r][2*p] = t.x; a[r][2*p+1] = t.y;
        }
#pragma unroll
    for (int r = 0; r < 4; r++)
#pragma unroll
        for (int o = 0; o < 16; o++)
#pragma unroll
            for (int off = 16; off; off >>= 1)
                a[r][o] += __shfl_xor_sync(0xffffffffu, a[r][o], off);
    __shared__ float red[8][64];
    int warp = threadIdx.x >> 5, lane = threadIdx.x & 31;
    if (lane == 0)
#pragma unroll
        for (int r = 0; r < 4; r++)
#pragma unroll
            for (int o = 0; o < 16; o++) red[warp][r*16+o] = a[r][o];
    __syncthreads();
    if (threadIdx.x < 64) {
        float s = 0.f;
#pragma unroll
        for (int w = 0; w < 8; w++) s += red[w][threadIdx.x];
        int r = threadIdx.x >> 4, o = threadIdx.x & 15;
        float sg = 1.f / (1.f + __expf(-s));
        if (which == 0) g_beta[(size_t)(row0+r) * 16 + o] = sg;
        else            g_gsw [(size_t)(row0+r) * 16 + o] = s * sg;
    }
}

// ============ K2: l2 norm ============
__global__ __launch_bounds__(256) void l2norm_kernel(
    const float* __restrict__ q, const float* __restrict__ k)
{
    int gw = (blockIdx.x << 3) + (threadIdx.x >> 5);
    int lane = threadIdx.x & 31;
    int which = (gw >= ROWS_) ? 1 : 0;
    int r = which ? (gw - ROWS_) : gw;
    const float* src = which ? k : q;
    float* dst = which ? g_kn : g_qn;
    float4 v = *(const float4*)(src + (size_t)r * 128 + lane * 4);
    float s = v.x*v.x + v.y*v.y + v.z*v.z + v.w*v.w;
#pragma unroll
    for (int off = 16; off; off >>= 1) s += __shfl_xor_sync(0xffffffffu, s, off);
    float inv = rsqrtf(s + 1e-6f);
    if (!which) inv *= 0.08838834764831845f;
    v.x *= inv; v.y *= inv; v.z *= inv; v.w *= inv;
    *(float4*)(dst + (size_t)r * 128 + lane * 4) = v;
}

// ============ K3: per-chunk UT transform (vectorized sT GEMMs) ============
#define CHUNK_SMEM ((128*68 + 64*132 + 64*68 + 64*68 + 64) * 4)
__global__ __launch_bounds__(256) void chunk_kernel(const float* __restrict__ v)
{
    extern __shared__ float sm[];
    float* sKT = sm;               // [128][68]
    float* sBuf= sKT + 128*68;     // [64][132]  staging K -> V -> Q
    float* sL  = sBuf + 64*132;    // [64][68]
    float* sT  = sL + 64*68;       // [64][68]
    float* sb  = sT + 64*68;       // [64]
    int idx = blockIdx.x;
    int n = idx & 63, h = (idx >> 6) & 15, b = idx >> 10;
    int t0 = n * 64;
    int tid = threadIdx.x;
    size_t rowbase = ((size_t)(b * T_ + t0) * H_ + h) * 128;

    // 1: K via cp.async
#pragma unroll
    for (int i = 0; i < 8; i++) {
        int f = tid + i*256; int row = f >> 5, c4 = f & 31;
        cpa16(&sBuf[row*132 + c4*4], &g_kn[rowbase + (size_t)row*2048 + c4*4]);
    }
    CPA_COMMIT();
    if (tid < 64) sb[tid] = g_beta[(size_t)(b*T_ + t0 + tid) * H_ + h];
    CPA_WAIT0(); __syncthreads();

    // 2: transpose -> sKT
    for (int e = tid; e < 2048; e += 256) {
        int c = e & 127, rb = e >> 7;
        float4 vv;
        vv.x = sBuf[(rb*4+0)*132 + c]; vv.y = sBuf[(rb*4+1)*132 + c];
        vv.z = sBuf[(rb*4+2)*132 + c]; vv.w = sBuf[(rb*4+3)*132 + c];
        *(float4*)&sKT[c*68 + rb*4] = vv;
    }
    __syncthreads();

    // 3: L = diag(beta) * strict_tril(K K^T)
    int ty = tid >> 4, tx = tid & 15;
    if (tx <= ty) {
        int r0 = ty*4, c0 = tx*4;
        u64 a[4][2] = {};
        for (int kk = 0; kk < 128; kk++) {
            const float* rp = &sKT[kk*68];
            float4 av = *(const float4*)(rp + r0);
            ulonglong2 bp = *(const ulonglong2*)(rp + c0);
            u64 A;
            A = pk2(av.x,av.x); fma2(a[0][0],A,bp.x); fma2(a[0][1],A,bp.y);
            A = pk2(av.y,av.y); fma2(a[1][0],A,bp.x); fma2(a[1][1],A,bp.y);
            A = pk2(av.z,av.z); fma2(a[2][0],A,bp.x); fma2(a[2][1],A,bp.y);
            A = pk2(av.w,av.w); fma2(a[3][0],A,bp.x); fma2(a[3][1],A,bp.y);
        }
#pragma unroll
        for (int i = 0; i < 4; i++) {
            int rr = r0 + i; float br = sb[rr];
            float2 p0 = up2(a[i][0]), p1 = up2(a[i][1]);
            float vals[4] = {p0.x, p0.y, p1.x, p1.y};
#pragma unroll
            for (int j = 0; j < 4; j++) {
                int cc = c0 + j;
                sL[rr*68 + cc] = (cc < rr) ? br * vals[j] : 0.f;
            }
        }
    }
    __syncthreads();

    // 4: (I+L) T' = diag(beta), forward substitution
    if (tid < 64) {
        int c = tid; float bc = sb[c];
        for (int i = 0; i < 64; i++) {
            const float* Li = &sL[i*68];
            float v0 = 0.f, v1 = 0.f, v2 = 0.f, v3 = 0.f;
            int j = c;
            for (; j + 3 < i; j += 4) {
                v0 -= Li[j  ] * sT[(j  )*68 + c];
                v1 -= Li[j+1] * sT[(j+1)*68 + c];
                v2 -= Li[j+2] * sT[(j+2)*68 + c];
                v3 -= Li[j+3] * sT[(j+3)*68 + c];
            }
            for (; j < i; j++) v0 -= Li[j] * sT[j*68 + c];
            sT[i*68 + c] = ((i == c) ? bc : 0.f) + v0 + v1 + v2 + v3;
        }
    }
    __syncthreads();

    int wid = tid >> 5, lane = tid & 31;
    // 5: w = T' @ K -> g_wq w-half (sBuf holds K); float4 sT fetch, j-unroll 4
    {
        int r0 = wid*8, c0 = lane*4;
        u64 acc[8][2] = {};
        for (int j = 0; j < 64; j += 4) {
            ulonglong2 bp0 = *(const ulonglong2*)&sBuf[(j  )*132 + c0];
            ulonglong2 bp1 = *(const ulonglong2*)&sBuf[(j+1)*132 + c0];
            ulonglong2 bp2 = *(const ulonglong2*)&sBuf[(j+2)*132 + c0];
            ulonglong2 bp3 = *(const ulonglong2*)&sBuf[(j+3)*132 + c0];
#pragma unroll
            for (int i = 0; i < 8; i++) {
                float4 a = *(const float4*)&sT[(r0+i)*68 + j];
                u64 A;
                A = pk2(a.x,a.x); fma2(acc[i][0],A,bp0.x); fma2(acc[i][1],A,bp0.y);
                A = pk2(a.y,a.y); fma2(acc[i][0],A,bp1.x); fma2(acc[i][1],A,bp1.y);
                A = pk2(a.z,a.z); fma2(acc[i][0],A,bp2.x); fma2(acc[i][1],A,bp2.y);
                A = pk2(a.w,a.w); fma2(acc[i][0],A,bp3.x); fma2(acc[i][1],A,bp3.y);
            }
        }
#pragma unroll
        for (int i = 0; i < 8; i++) {
            float2 p0 = up2(acc[i][0]), p1 = up2(acc[i][1]);
            *(float4*)&g_wq[(size_t)idx*16384 + (size_t)(r0+i)*256 + c0] =
                make_float4(p0.x,p0.y,p1.x,p1.y);
        }
    }
    __syncthreads();

    // 6: V via cp.async
#pragma unroll
    for (int i = 0; i < 8; i++) {
        int f = tid + i*256; int row = f >> 5, c4 = f & 31;
        cpa16(&sBuf[row*132 + c4*4], &v[rowbase + (size_t)row*2048 + c4*4]);
    }
    CPA_COMMIT(); CPA_WAIT0(); __syncthreads();

    // 7: u = T' @ V ; float4 sT fetch, j-unroll 4
    {
        int r0 = wid*8, c0 = lane*4;
        u64 acc[8][2] = {};
        for (int j = 0; j < 64; j += 4) {
            ulonglong2 bp0 = *(const ulonglong2*)&sBuf[(j  )*132 + c0];
            ulonglong2 bp1 = *(const ulonglong2*)&sBuf[(j+1)*132 + c0];
            ulonglong2 bp2 = *(const ulonglong2*)&sBuf[(j+2)*132 + c0];
            ulonglong2 bp3 = *(const ulonglong2*)&sBuf[(j+3)*132 + c0];
#pragma unroll
            for (int i = 0; i < 8; i++) {
                float4 a = *(const float4*)&sT[(r0+i)*68 + j];
                u64 A;
                A = pk2(a.x,a.x); fma2(acc[i][0],A,bp0.x); fma2(acc[i][1],A,bp0.y);
                A = pk2(a.y,a.y); fma2(acc[i][0],A,bp1.x); fma2(acc[i][1],A,bp1.y);
                A = pk2(a.z,a.z); fma2(acc[i][0],A,bp2.x); fma2(acc[i][1],A,bp2.y);
                A = pk2(a.w,a.w); fma2(acc[i][0],A,bp3.x); fma2(acc[i][1],A,bp3.y);
            }
        }
#pragma unroll
        for (int i = 0; i < 8; i++) {
            float2 p0 = up2(acc[i][0]), p1 = up2(acc[i][1]);
            *(float4*)&g_u[(size_t)idx*8192 + (r0+i)*128 + c0] =
                make_float4(p0.x,p0.y,p1.x,p1.y);
        }
    }
    __syncthreads();

    // 8: Q via cp.async
#pragma unroll
    for (int i = 0; i < 8; i++) {
        int f = tid + i*256; int row = f >> 5, c4 = f & 31;
        cpa16(&sBuf[row*132 + c4*4], &g_qn[rowbase + (size_t)row*2048 + c4*4]);
    }
    CPA_COMMIT(); CPA_WAIT0(); __syncthreads();

    // 8.5: q copy -> g_wq q-half (coalesced)
    for (int e = tid; e < 2048; e += 256) {
        int row = e >> 5, c4 = e & 31;
        float4 qv = *(const float4*)&sBuf[row*132 + c4*4];
        *(float4*)&g_wq[(size_t)idx*16384 + (size_t)row*256 + 128 + c4*4] = qv;
    }

    // 9: attn = tril(Q K^T)
    {
        int r0 = ty*4, c0 = tx*4;
        if (tx <= ty) {
            u64 a[4][2] = {};
            for (int kk = 0; kk < 128; kk++) {
                ulonglong2 bp = *(const ulonglong2*)&sKT[kk*68 + c0];
                float q0 = sBuf[(r0+0)*132 + kk];
                float q1 = sBuf[(r0+1)*132 + kk];
                float q2 = sBuf[(r0+2)*132 + kk];
                float q3 = sBuf[(r0+3)*132 + kk];
                u64 A;
                A = pk2(q0,q0); fma2(a[0][0],A,bp.x); fma2(a[0][1],A,bp.y);
                A = pk2(q1,q1); fma2(a[1][0],A,bp.x); fma2(a[1][1],A,bp.y);
                A = pk2(q2,q2); fma2(a[2][0],A,bp.x); fma2(a[2][1],A,bp.y);
                A = pk2(q3,q3); fma2(a[3][0],A,bp.x); fma2(a[3][1],A,bp.y);
            }
#pragma unroll
            for (int i = 0; i < 4; i++) {
                float2 p0 = up2(a[i][0]), p1 = up2(a[i][1]);
                float vals[4] = {p0.x, p0.y, p1.x, p1.y};
#pragma unroll
                for (int j = 0; j < 4; j++)
                    g_attn[(size_t)idx*4096 + (r0+i)*64 + c0+j] =
                        (c0+j <= r0+i) ? vals[j] : 0.f;
            }
        } else {
#pragma unroll
            for (int i = 0; i < 4; i++)
#pragma unroll
                for (int j = 0; j < 4; j++)
                    g_attn[(size_t)idx*4096 + (r0+i)*64 + c0+j] = 0.f;
        }
    }
}

// ============ K4: inter-chunk scan (split-half wq rows, r2c4 / 256 thr) ============
#define SCAN_SMEM ((128*36 + 64*264 + 64*132 + 64*68 + 64*36) * 4)
__global__ __launch_bounds__(256) void scan_kernel()
{
    extern __shared__ float sm[];
    float* sS  = sm;                // [128][36]
    float* sWQ = sS  + 128*36;      // [64][264]  (256 data + 8 pad)
    float* sK  = sWQ + 64*264;      // [64][132]
    float* sA  = sK  + 64*132;      // [64][68]
    float* sVi = sA  + 64*68;       // [64][36]

    int vg = blockIdx.x, h = blockIdx.y, b = blockIdx.z;
    int v0 = vg * 32;
    int tid = threadIdx.x;
    int rq = tid >> 3, c0 = (tid & 7) * 4;
    int r0 = rq * 2;               // phase A/B rows
    int k0 = rq * 4;               // phase C k-rows
    int taskbase = (b*16 + h) * 64;

    for (int e = tid; e < 128*36; e += 256) sS[e] = 0.f;
    u64 sreg[4][2] = {};

    // prologue: G1 = {WQ,A}(0), G2 = {K}(0)
    {
        size_t rb0 = ((size_t)(b*T_) * H_ + h) * 128;
#pragma unroll
        for (int i = 0; i < 16; i++) {
            int f = tid + i*256;
            int row = f >> 6, jj = f & 63;
            cpa16(&sWQ[row*264 + jj*4], g_wq + (size_t)taskbase*16384 + f*4);
        }
#pragma unroll
        for (int i = 0; i < 4; i++) {
            int f = tid + i*256;
            cpa16(&sA[(f>>4)*68 + (f&15)*4], g_attn + (size_t)taskbase*4096 + f*4);
        }
        CPA_COMMIT();
#pragma unroll
        for (int i = 0; i < 8; i++) {
            int f = tid + i*256; int row = f >> 5, c4 = f & 31;
            cpa16(&sK[row*132 + c4*4], g_kn + rb0 + (size_t)row*2048 + c4*4);
        }
        CPA_COMMIT();
    }
    float4 ruA, ruB;
    {
        size_t ub = (size_t)taskbase*8192 + (size_t)r0*128 + v0 + c0;
        ruA = *(const float4*)&g_u[ub];
        ruB = *(const float4*)&g_u[ub + 128];
    }

    for (int n = 0; n < 64; n++) {
        int np = min(n + 1, 63);
        int taskp = taskbase + np;
        size_t rowbase  = ((size_t)(b*T_ + n*64)  * H_ + h) * 128;

        CPA_WAIT1();               // WQ,A(n) ready
        __syncthreads();

        // prefetch u(n+1)
        float4 ruA2, ruB2;
        {
            size_t ub = (size_t)taskp*8192 + (size_t)r0*128 + v0 + c0;
            ruA2 = *(const float4*)&g_u[ub];
            ruB2 = *(const float4*)&g_u[ub + 128];
        }

        // ---- phase A: vi = u - w@S ; partial o = q@S ----
        u64 aw0=0, aw1=0, aw2=0, aw3=0;
        u64 aq0=0, aq1=0, aq2=0, aq3=0;
        {
            const float* wr0 = &sWQ[r0*264];
            const float* wr1 = wr0 + 264;
            const float* qr0 = wr0 + 128;
            const float* qr1 = wr1 + 128;
            for (int k = 0; k < 128; k += 4) {
                ulonglong2 s0 = *(const ulonglong2*)&sS[(k  )*36 + c0];
                ulonglong2 s1 = *(const ulonglong2*)&sS[(k+1)*36 + c0];
                ulonglong2 s2 = *(const ulonglong2*)&sS[(k+2)*36 + c0];
                ulonglong2 s3 = *(const ulonglong2*)&sS[(k+3)*36 + c0];
                float4 w0 = *(const float4*)&wr0[k];
                float4 w1 = *(const float4*)&wr1[k];
                float4 q0 = *(const float4*)&qr0[k];
                float4 q1 = *(const float4*)&qr1[k];
                u64 A;
                A = pk2(w0.x,w0.x); fma2(aw0,A,s0.x); fma2(aw1,A,s0.y);
                A = pk2(w1.x,w1.x); fma2(aw2,A,s0.x); fma2(aw3,A,s0.y);
                A = pk2(q0.x,q0.x); fma2(aq0,A,s0.x); fma2(aq1,A,s0.y);
                A = pk2(q1.x,q1.x); fma2(aq2,A,s0.x); fma2(aq3,A,s0.y);
                A = pk2(w0.y,w0.y); fma2(aw0,A,s1.x); fma2(aw1,A,s1.y);
                A = pk2(w1.y,w1.y); fma2(aw2,A,s1.x); fma2(aw3,A,s1.y);
                A = pk2(q0.y,q0.y); fma2(aq0,A,s1.x); fma2(aq1,A,s1.y);
                A = pk2(q1.y,q1.y); fma2(aq2,A,s1.x); fma2(aq3,A,s1.y);
                A = pk2(w0.z,w0.z); fma2(aw0,A,s2.x); fma2(aw1,A,s2.y);
                A = pk2(w1.z,w1.z); fma2(aw2,A,s2.x); fma2(aw3,A,s2.y);
                A = pk2(q0.z,q0.z); fma2(aq0,A,s2.x); fma2(aq1,A,s2.y);
                A = pk2(q1.z,q1.z); fma2(aq2,A,s2.x); fma2(aq3,A,s2.y);
                A = pk2(w0.w,w0.w); fma2(aw0,A,s3.x); fma2(aw1,A,s3.y);
                A = pk2(w1.w,w1.w); fma2(aw2,A,s3.x); fma2(aw3,A,s3.y);
                A = pk2(q0.w,q0.w); fma2(aq0,A,s3.x); fma2(aq1,A,s3.y);
                A = pk2(q1.w,q1.w); fma2(aq2,A,s3.x); fma2(aq3,A,s3.y);
            }
        }
        {
            float2 p0 = up2(aw0), p1 = up2(aw1), p2 = up2(aw2), p3 = up2(aw3);
            *(float4*)&sVi[(r0  )*36 + c0] =
                make_float4(ruA.x - p0.x, ruA.y - p0.y, ruA.z - p1.x, ruA.w - p1.y);
            *(float4*)&sVi[(r0+1)*36 + c0] =
                make_float4(ruB.x - p2.x, ruB.y - p2.y, ruB.z - p3.x, ruB.w - p3.y);
        }
        ruA = ruA2; ruB = ruB2;
        __syncthreads();           // sVi published

        // ---- phase B: o = q@S + attn @ vi ----
        {
            const float* ar0 = &sA[r0*68];
            const float* ar1 = ar0 + 68;
            for (int j = 0; j <= r0 + 1; j++) {
                ulonglong2 vv = *(const ulonglong2*)&sVi[j*36 + c0];
                float a0 = ar0[j], a1 = ar1[j];
                u64 A0 = pk2(a0,a0); fma2(aq0,A0,vv.x); fma2(aq1,A0,vv.y);
                u64 A1 = pk2(a1,a1); fma2(aq2,A1,vv.x); fma2(aq3,A1,vv.y);
            }
            float2 p0 = up2(aq0), p1 = up2(aq1), p2 = up2(aq2), p3 = up2(aq3);
            size_t ob = rowbase + (size_t)r0*2048 + v0 + c0;
            *(float4*)&g_o[ob]        = make_float4(p0.x, p0.y, p1.x, p1.y);
            *(float4*)&g_o[ob + 2048] = make_float4(p2.x, p2.y, p3.x, p3.y);
        }
        __syncthreads();           // sA,sWQ dead -> refill

        // issue G1(n+1) = {WQ,A}
#pragma unroll
        for (int i = 0; i < 16; i++) {
            int f = tid + i*256;
            int row = f >> 6, jj = f & 63;
            cpa16(&sWQ[row*264 + jj*4], g_wq + (size_t)taskp*16384 + f*4);
        }
#pragma unroll
        for (int i = 0; i < 4; i++) {
            int f = tid + i*256;
            cpa16(&sA[(f>>4)*68 + (f&15)*4], g_attn + (size_t)taskp*4096 + f*4);
        }
        CPA_COMMIT();

        CPA_WAIT1();               // K(n) ready
        __syncthreads();

        // ---- phase C: S += K^T @ vi (register tile) ----
        {
#pragma unroll 2
            for (int c = 0; c < 64; c++) {
                float4 kv = *(const float4*)&sK[c*132 + k0];
                float4 vv = *(const float4*)&sVi[c*36 + c0];
                u64 vp0 = pk2(vv.x, vv.y), vp1 = pk2(vv.z, vv.w);
                u64 A;
                A = pk2(kv.x,kv.x); fma2(sreg[0][0], A, vp0); fma2(sreg[0][1], A, vp1);
                A = pk2(kv.y,kv.y); fma2(sreg[1][0], A, vp0); fma2(sreg[1][1], A, vp1);
                A = pk2(kv.z,kv.z); fma2(sreg[2][0], A, vp0); fma2(sreg[2][1], A, vp1);
                A = pk2(kv.w,kv.w); fma2(sreg[3][0], A, vp0); fma2(sreg[3][1], A, vp1);
            }
#pragma unroll
            for (int i = 0; i < 4; i++) {
                float2 a = up2(sreg[i][0]), bb = up2(sreg[i][1]);
                *(float4*)&sS[(k0+i)*36 + c0] = make_float4(a.x, a.y, bb.x, bb.y);
            }
        }
        __syncthreads();           // sK reads done -> refill

        // issue G2(n+1) = {K}
        {
            size_t rowbasep = ((size_t)(b*T_ + np*64) * H_ + h) * 128;
#pragma unroll
            for (int i = 0; i < 8; i++) {
                int f = tid + i*256; int row = f >> 5, c4 = f & 31;
                cpa16(&sK[row*132 + c4*4], g_kn + rowbasep + (size_t)row*2048 + c4*4);
            }
            CPA_COMMIT();
        }
    }
}

// ============ K5: RMSNorm * gate + per-head projection ============
#define OUT_SMEM ((128*132 + 64*132) * 4)
__global__ __launch_bounds__(256) void out_kernel(
    const float* __restrict__ norm_w, const float* __restrict__ proj,
    float* __restrict__ out)
{
    extern __shared__ float sm[];
    float* sP = sm;
    float* sO = sP + 128*132;
    int h = blockIdx.y;
    int tid = threadIdx.x, wid = tid >> 5, lane = tid & 31;
    const float* Ph = proj + (size_t)h * 16384;
    for (int e = tid; e < 4096; e += 256) {
        int row = e >> 5, c4 = e & 31;
        *(float4*)&sP[row*132 + c4*4] = *(const float4*)&Ph[row*128 + c4*4];
    }
    float4 nw = *(const float4*)&norm_w[lane*4];
    __syncthreads();

    for (int grp = 0; grp < 2; grp++) {
        int bt0 = blockIdx.x*128 + grp*64;
        int wr = wid * 8;
        for (int i = 0; i < 8; i++) {
            int bt = bt0 + wr + i;
            size_t ob = ((size_t)bt * H_ + h) * 128;
            float4 ov = *(const float4*)&g_o[ob + lane*4];
            float ss = ov.x*ov.x + ov.y*ov.y + ov.z*ov.z + ov.w*ov.w;
#pragma unroll
            for (int off = 16; off; off >>= 1)
                ss += __shfl_xor_sync(0xffffffffu, ss, off);
            float rms = rsqrtf(ss * (1.f/128.f) + 1e-5f);
            float s = rms * g_gsw[(size_t)bt * H_ + h];
            float* orow = &sO[(wr+i)*132];
            orow[lane*4+0] = ov.x * s * nw.x;
            orow[lane*4+1] = ov.y * s * nw.y;
            orow[lane*4+2] = ov.z * s * nw.z;
            orow[lane*4+3] = ov.w * s * nw.w;
        }
        __syncwarp();
        u64 acc[8][2] = {};
        for (int vv = 0; vv < 128; vv++) {
            float4 p = *(const float4*)&sP[vv*132 + lane*4];
            u64 p01 = pk2(p.x, p.y), p23 = pk2(p.z, p.w);
#pragma unroll
            for (int i = 0; i < 8; i++) {
                float ovv = sO[(wr+i)*132 + vv];
                u64 A = pk2(ovv, ovv);
                fma2(acc[i][0], A, p01);
                fma2(acc[i][1], A, p23);
            }
        }
#pragma unroll
        for (int i = 0; i < 8; i++) {
            int bt = bt0 + wr + i;
            float2 p0 = up2(acc[i][0]), p1 = up2(acc[i][1]);
            *(float4*)&out[(size_t)bt*2048 + h*128 + lane*4] =
                make_float4(p0.x, p0.y, p1.x, p1.y);
        }
        __syncwarp();
    }
}

// ============ launch ============
extern "C" void kernel_launch(void* const* d_in, const int* in_sizes, int n_in,
                              void* d_out, int out_size)
{
    const float* hab  = (const float*)d_in[0];
    const float* hg   = (const float*)d_in[1];
    const float* q    = (const float*)d_in[2];
    const float* k    = (const float*)d_in[3];
    const float* v    = (const float*)d_in[4];
    const float* Wb   = (const float*)d_in[5];
    const float* Wg   = (const float*)d_in[6];
    const float* onw  = (const float*)d_in[7];
    const float* proj = (const float*)d_in[8];
    float* out = (float*)d_out;

    cudaFuncSetAttribute(chunk_kernel, cudaFuncAttributeMaxDynamicSharedMemorySize, CHUNK_SMEM);
    cudaFuncSetAttribute(scan_kernel,  cudaFuncAttributeMaxDynamicSharedMemorySize, SCAN_SMEM);
    cudaFuncSetAttribute(out_kernel,   cudaFuncAttributeMaxDynamicSharedMemorySize, OUT_SMEM);

    proj_kernel<<<dim3(B_*T_/4, 2), 256>>>(hab, hg, Wb, Wg);
    l2norm_kernel<<<(2*ROWS_)/8, 256>>>(q, k);
    chunk_kernel<<<NTASK_, 256, CHUNK_SMEM>>>(v);
    scan_kernel<<<dim3(4, H_, B_), 256, SCAN_SMEM>>>();
    out_kernel<<<dim3(64, H_), 256, OUT_SMEM>>>(onw, proj, out);
}